// round 5
// baseline (speedup 1.0000x reference)
#include <cuda_runtime.h>
#include <cstdint>

#define Bn 2048
#define Tn 2048
#define TB (Tn * Bn)
#define NVOCAB 32000

typedef unsigned long long f2;

// Static device scratch (no runtime allocations allowed)
// Per (dir, t, b, half): float4 {0.5*xr_u0, 0.5*xr_u1, 0.5*xz_u0, 0.5*xz_u1}
//                        float2 {xn_u0, xn_u1}
__device__ float4 g_xiP[2][(size_t)TB * 2];
__device__ float2 g_xiN2[2][(size_t)TB * 2];
__device__ float4 g_xo[2][TB];               // out-GRU projections per dir [t*Bn+b]
__device__ int    g_is64;

static __device__ __forceinline__ f2 pk2(float a, float b) {
    f2 r; asm("mov.b64 %0,{%1,%2};" : "=l"(r) : "f"(a), "f"(b)); return r;
}
static __device__ __forceinline__ void upk2(f2 v, float& a, float& b) {
    asm("mov.b64 {%0,%1},%2;" : "=f"(a), "=f"(b) : "l"(v));
}
static __device__ __forceinline__ f2 fma2(f2 a, f2 b, f2 c) {
    f2 r; asm("fma.rn.f32x2 %0,%1,%2,%3;" : "=l"(r) : "l"(a), "l"(b), "l"(c)); return r;
}
static __device__ __forceinline__ float tanhap(float x) {
    float r; asm("tanh.approx.f32 %0,%1;" : "=f"(r) : "f"(x)); return r;
}
static __device__ __forceinline__ uint32_t s2u(const void* p) {
    uint32_t a;
    asm("{ .reg .u64 t; cvta.to.shared.u64 t, %1; cvt.u32.u64 %0, t; }" : "=r"(a) : "l"(p));
    return a;
}
static __device__ __forceinline__ void cpa16(uint32_t s, const void* g) {
    asm volatile("cp.async.ca.shared.global [%0], [%1], 16;" :: "r"(s), "l"(g) : "memory");
}
static __device__ __forceinline__ void cpa_commit() {
    asm volatile("cp.async.commit_group;" ::: "memory");
}
template <int N> static __device__ __forceinline__ void cpa_wait() {
    asm volatile("cp.async.wait_group %0;" :: "n"(N) : "memory");
}

// ---------------------------------------------------------------------------
// Detect x dtype: int64 => every odd 32-bit word (high half) is 0 (tokens<32000)
__global__ void k_detect(const unsigned int* xw) {
    if (threadIdx.x == 0 && blockIdx.x == 0) {
        int all0 = 1;
        for (int i = 0; i < 64; i++)
            if (xw[2 * i + 1] != 0u) { all0 = 0; break; }
        g_is64 = all0;
    }
}

// ---------------------------------------------------------------------------
// xi precompute (fused transpose). One thread per (t,b), b fastest.
//   dir0 at index t*Bn+b ; dir1 at (Tn-1-t)*Bn+b. Split per half-chain.
__global__ void k_xi(const void* __restrict__ xv, const float* __restrict__ emb,
                     const float* __restrict__ WihF, const float* __restrict__ bihF,
                     const float* __restrict__ bhhF,
                     const float* __restrict__ WihB, const float* __restrict__ bihB,
                     const float* __restrict__ bhhB) {
    __shared__ float sw[2][12][4];
    __shared__ float sb[2][12];
    int tid = threadIdx.x;
    if (tid < 96) {
        int d = tid / 48, g = (tid % 48) / 4, j = tid & 3;
        const float* W = d ? WihB : WihF;
        sw[d][g][j] = W[g * 4 + j] * (g < 8 ? 0.5f : 1.0f);
    }
    if (tid < 24) {
        int d = tid / 12, g = tid % 12;
        const float* bi = d ? bihB : bihF;
        const float* bh = d ? bhhB : bhhF;
        float v = bi[g] + (g < 8 ? bh[g] : 0.0f);
        sb[d][g] = (g < 8 ? 0.5f : 1.0f) * v;
    }
    __syncthreads();

    int id = blockIdx.x * blockDim.x + threadIdx.x;   // t*Bn + b
    int b = id & (Bn - 1);
    int t = id >> 11;
    int tok;
    if (g_is64) tok = (int)((const long long*)xv)[(size_t)b * Tn + t];
    else        tok = ((const int*)xv)[(size_t)b * Tn + t];
    float4 e = *(const float4*)&emb[(size_t)tok * 4];

    int idxs[2] = { id, (Tn - 1 - t) * Bn + b };
    #pragma unroll
    for (int d = 0; d < 2; d++) {
        float o[12];
        #pragma unroll
        for (int g = 0; g < 12; g++) {
            float s = sb[d][g];
            s = fmaf(sw[d][g][0], e.x, s);
            s = fmaf(sw[d][g][1], e.y, s);
            s = fmaf(sw[d][g][2], e.z, s);
            s = fmaf(sw[d][g][3], e.w, s);
            o[g] = s;
        }
        size_t ix = (size_t)idxs[d] * 2;
        g_xiP[d][ix]      = make_float4(o[0], o[1], o[4],  o[5]);
        g_xiP[d][ix + 1]  = make_float4(o[2], o[3], o[6],  o[7]);
        g_xiN2[d][ix]     = make_float2(o[8], o[9]);
        g_xiN2[d][ix + 1] = make_float2(o[10], o[11]);
    }
}

// ---------------------------------------------------------------------------
// Kernel 1: fwd + bwd GRU chains. Each chain split across lane pair (l, l+16).
// 64-thread blocks: 2 warps -> 2 SMSPs per SM. LDG register double-buffer.
__global__ void __launch_bounds__(64, 1)
k_dirs(const float* __restrict__ WhhF, const float* __restrict__ bhhF,
       const float* __restrict__ WhhB, const float* __restrict__ bhhB,
       const float* __restrict__ WihO, const float* __restrict__ bihO,
       const float* __restrict__ bhhO) {
    int lane  = threadIdx.x & 31;
    int w     = threadIdx.x >> 5;
    int half  = lane >> 4;                       // 0: units 0,1 ; 1: units 2,3
    int chain = (blockIdx.x * 2 + w) * 16 + (lane & 15);
    int dir   = chain >> 11;                     // warp-uniform
    int row   = chain & (Bn - 1);
    int u0    = 2 * half;

    const float* Whh = dir ? WhhB : WhhF;
    const float* bhh = dir ? bhhB : bhhF;

    // Per-lane weights, permuted so local h order (ha,hb,pa,pb) matches:
    // local slot j corresponds to global unit (j + u0) & 3.
    f2 wr[4], wz[4], wn[4];
    #pragma unroll
    for (int j = 0; j < 4; j++) {
        int gj = (j + u0) & 3;                   // global unit for local slot j
        wr[j] = pk2(0.5f * Whh[(0 + u0) * 4 + gj], 0.5f * Whh[(1 + u0) * 4 + gj]);
        wz[j] = pk2(0.5f * Whh[(4 + u0) * 4 + gj], 0.5f * Whh[(5 + u0) * 4 + gj]);
        wn[j] = pk2(Whh[(8 + u0) * 4 + gj],        Whh[(9 + u0) * 4 + gj]);
    }
    const f2 bn = pk2(bhh[8 + u0], bhh[9 + u0]);

    // Output projection weights for this lane's 2 units (r,z scaled by 0.5).
    f2 wrz0 = pk2(0.5f * WihO[0 * 8 + dir * 4 + u0],     0.5f * WihO[1 * 8 + dir * 4 + u0]);
    f2 wrz1 = pk2(0.5f * WihO[0 * 8 + dir * 4 + u0 + 1], 0.5f * WihO[1 * 8 + dir * 4 + u0 + 1]);
    float won0 = WihO[2 * 8 + dir * 4 + u0];
    float won1 = WihO[2 * 8 + dir * 4 + u0 + 1];
    bool fold = (dir == 0) && (half == 0);       // fold biases exactly once
    f2 borz = fold ? pk2(0.5f * (bihO[0] + bhhO[0]), 0.5f * (bihO[1] + bhhO[1]))
                   : pk2(0.f, 0.f);
    float bon = fold ? bihO[2] : 0.f;

    const ulonglong2* pP = (const ulonglong2*)g_xiP[dir];
    const f2*         pN = (const f2*)g_xiN2[dir];
    float4*           xop = g_xo[dir];
    const int pidx = row * 2 + half;             // element index; stride 2*Bn per t

    ulonglong2 bP[2][4];
    f2         bNv[2][4];
    auto loadChunk = [&](int c, int s) {
        #pragma unroll
        for (int k = 0; k < 4; k++) {
            size_t e = (size_t)(4 * c + k) * (2 * Bn) + pidx;
            bP[s][k]  = pP[e];
            bNv[s][k] = pN[e];
        }
    };

    float ha = 0.f, hb = 0.f;                    // this lane's 2 hidden units
    loadChunk(0, 0);

    const int NC = Tn / 4;
    for (int c = 0; c < NC; c++) {
        int cur = c & 1;
        if (c + 1 < NC) loadChunk(c + 1, cur ^ 1);
        #pragma unroll
        for (int k = 0; k < 4; k++) {
            // exchange h with peer half-chain
            float pa = __shfl_xor_sync(0xffffffffu, ha, 16);
            float pb = __shfl_xor_sync(0xffffffffu, hb, 16);
            f2 q0 = pk2(ha, ha), q1 = pk2(hb, hb);
            f2 q2 = pk2(pa, pa), q3 = pk2(pb, pb);

            f2 ar = bP[cur][k].x;                // (0.5xr_u0, 0.5xr_u1)
            f2 az = bP[cur][k].y;                // (0.5xz_u0, 0.5xz_u1)
            f2 an = bn;

            ar = fma2(wr[0], q0, ar); ar = fma2(wr[1], q1, ar);
            ar = fma2(wr[2], q2, ar); ar = fma2(wr[3], q3, ar);
            az = fma2(wz[0], q0, az); az = fma2(wz[1], q1, az);
            az = fma2(wz[2], q2, az); az = fma2(wz[3], q3, az);
            an = fma2(wn[0], q0, an); an = fma2(wn[1], q1, an);
            an = fma2(wn[2], q2, an); an = fma2(wn[3], q3, an);

            float a0, a1; upk2(ar, a0, a1);
            float r0 = fmaf(0.5f, tanhap(a0), 0.5f);
            float r1 = fmaf(0.5f, tanhap(a1), 0.5f);
            float c0, c1; upk2(az, c0, c1);
            float z0 = fmaf(0.5f, tanhap(c0), 0.5f);
            float z1 = fmaf(0.5f, tanhap(c1), 0.5f);
            float hn0, hn1; upk2(an, hn0, hn1);
            float xn0, xn1; upk2(bNv[cur][k], xn0, xn1);

            float n0 = tanhap(fmaf(r0, hn0, xn0));
            float n1 = tanhap(fmaf(r1, hn1, xn1));

            ha = fmaf(z0, ha - n0, n0);
            hb = fmaf(z1, hb - n1, n1);

            // out-GRU projection partial for this lane's 2 units
            f2 prz = fma2(wrz0, pk2(ha, ha), fma2(wrz1, pk2(hb, hb), borz));
            float pn = fmaf(won0, ha, fmaf(won1, hb, bon));
            float pr, pz; upk2(prz, pr, pz);
            pr += __shfl_xor_sync(0xffffffffu, pr, 16);
            pz += __shfl_xor_sync(0xffffffffu, pz, 16);
            pn += __shfl_xor_sync(0xffffffffu, pn, 16);

            if (lane < 16) {
                int t  = 4 * c + k;
                int tt = dir ? (Tn - 1 - t) : t;
                xop[(size_t)tt * Bn + row] = make_float4(pr, pz, pn, 0.f);
            }
        }
    }
}

// ---------------------------------------------------------------------------
// Kernel 2: output GRU (H=1). Per step just adds the two dirs' projections.
#define OSTAGES 4
#define OCK 8
__global__ void __launch_bounds__(32, 1)
k_out(const float* __restrict__ Who, const float* __restrict__ bho,
      float* __restrict__ out) {
    __shared__ char sbuf[OSTAGES * OCK * 2 * 32 * 16];   // 32 KB
    uint32_t sbase = s2u(sbuf);

    int lane = threadIdx.x;
    int row = blockIdx.x * 32 + lane;

    float wrh = 0.5f * Who[0], wzh = 0.5f * Who[1], wnh = Who[2];
    float bhn = bho[2];
    float h = 0.f;

    auto slot = [&](int st, int k, int a) -> uint32_t {
        return sbase + (uint32_t)((((st * OCK + k) * 2 + a) * 32 + lane) * 16);
    };
    auto issue = [&](int c) {
        int st = c & (OSTAGES - 1);
        #pragma unroll
        for (int k = 0; k < OCK; k++) {
            int ix = (OCK * c + k) * Bn + row;
            cpa16(slot(st, k, 0), &g_xo[0][ix]);
            cpa16(slot(st, k, 1), &g_xo[1][ix]);
        }
    };

    issue(0); cpa_commit();
    issue(1); cpa_commit();
    issue(2); cpa_commit();

    const int NC = Tn / OCK;
    float4* outv = (float4*)out;
    for (int c = 0; c < NC; c++) {
        if (c + 3 < NC) issue(c + 3);
        cpa_commit();
        cpa_wait<3>();
        int st = c & (OSTAGES - 1);
        float o[OCK];
        #pragma unroll
        for (int k = 0; k < OCK; k++) {
            float4 f = *(const float4*)(sbuf + (slot(st, k, 0) - sbase));
            float4 b = *(const float4*)(sbuf + (slot(st, k, 1) - sbase));
            float ar = f.x + b.x;
            float az = f.y + b.y;
            float ax = f.z + b.z;
            float r  = fmaf(0.5f, tanhap(fmaf(wrh, h, ar)), 0.5f);
            float z  = fmaf(0.5f, tanhap(fmaf(wzh, h, az)), 0.5f);
            float hn = fmaf(wnh, h, bhn);
            float n  = tanhap(fmaf(r, hn, ax));
            h = fmaf(z, h - n, n);
            o[k] = fmaf(0.5f, tanhap(0.5f * h), 0.5f);
        }
        #pragma unroll
        for (int q = 0; q < OCK / 4; q++)
            outv[(size_t)row * (Tn / 4) + c * (OCK / 4) + q] =
                make_float4(o[4 * q], o[4 * q + 1], o[4 * q + 2], o[4 * q + 3]);
    }
}

// ---------------------------------------------------------------------------
extern "C" void kernel_launch(void* const* d_in, const int* in_sizes, int n_in,
                              void* d_out, int out_size) {
    const void*  x    = d_in[0];
    const float* emb  = (const float*)d_in[1];
    const float* WihF = (const float*)d_in[2];
    const float* WhhF = (const float*)d_in[3];
    const float* bihF = (const float*)d_in[4];
    const float* bhhF = (const float*)d_in[5];
    const float* WihB = (const float*)d_in[6];
    const float* WhhB = (const float*)d_in[7];
    const float* bihB = (const float*)d_in[8];
    const float* bhhB = (const float*)d_in[9];
    const float* WihO = (const float*)d_in[10];
    const float* WhhO = (const float*)d_in[11];
    const float* bihO = (const float*)d_in[12];
    const float* bhhO = (const float*)d_in[13];

    k_detect<<<1, 32>>>((const unsigned int*)x);
    k_xi<<<TB / 256, 256>>>(x, emb, WihF, bihF, bhhF, WihB, bihB, bhhB);
    k_dirs<<<128, 64>>>(WhhF, bhhF, WhhB, bhhB, WihO, bihO, bhhO);
    k_out<<<Bn / 32, 32>>>(WhhO, bhhO, (float*)d_out);
}